// round 14
// baseline (speedup 1.0000x reference)
#include <cuda_runtime.h>
#include <math.h>

#define B_    128
#define SDEC  256
#define SENC  256
#define IDIM  256
#define HDIM  512
#define ODIM  256
#define G4H   2048
#define MROWS 32768   // B_*SDEC == B_*SENC

typedef unsigned long long ull;
typedef unsigned int u32;

// ---------------- scratch (device globals; no allocs allowed) ----------------
__device__ float g_xW [(size_t)MROWS * G4H];  // x@W_ih^T + biases, [m=b*256+t][col]
__device__ float g_xWf[(size_t)MROWS * G4H];  // fragment layout [t][blk][w][ni][lane][j]
__device__ float g_K [(size_t)MROWS * HDIM];  // tf32(enc@Wk^T + bk)
__device__ float g_V [(size_t)MROWS * HDIM];  // tf32(K@Wv^T + bv)
__device__ float g_H [(size_t)MROWS * HDIM];  // all h_t fp32 [b*256+t][u]
__device__ float g_Htf[(size_t)MROWS * HDIM]; // tf32(h) for Q projection
__device__ float g_Q [(size_t)MROWS * HDIM];  // tf32(H@Wq^T + bq)
__device__ float g_HC[(size_t)MROWS * HDIM];  // tf32(h + context)
__device__ float g_S [(size_t)B_ * SDEC * SENC]; // scores fp32 -> probs tf32
__device__ u32   g_hT2[2 * (HDIM / 2) * B_];  // h ping-pong bf16x2 pairs
__device__ float g_bsum[G4H];
__device__ float g_xtf [(size_t)B_ * SDEC * IDIM];   // tf32(x)
__device__ float g_etf [(size_t)B_ * SENC * HDIM];   // tf32(enc)
__device__ float g_Wihtf[G4H * IDIM];
__device__ float g_Wktf [HDIM * HDIM];
__device__ float g_Wvtf [HDIM * HDIM];
__device__ float g_Wqtf [HDIM * HDIM];
__device__ float g_Wfctf[ODIM * HDIM];
__device__ unsigned g_barc2[2];   // init barrier (relative-gen, replay-safe)
__device__ unsigned g_barg2[2];
__device__ unsigned g_barcA[2];   // per-step group barriers (absolute gen,
__device__ unsigned g_bargA[2];   //  reset in bias_sum each launch)
__device__ unsigned g_barcB[2];
__device__ unsigned g_bargB[2];

__device__ __forceinline__ float sigmoidf_(float x) { return 1.0f / (1.0f + __expf(-x)); }

__device__ __forceinline__ float totf32(float x) {
    u32 r;
    asm("cvt.rna.tf32.f32 %0, %1;" : "=r"(r) : "f"(x));
    return __uint_as_float(r);
}
__device__ __forceinline__ u32 pack_bf2(float lo, float hi) {
    u32 r;
    asm("cvt.rn.bf16x2.f32 %0, %1, %2;" : "=r"(r) : "f"(hi), "f"(lo));
    return r;
}
__device__ __forceinline__ void mma_tf32(float* c, const u32* a, const u32* b) {
    asm("mma.sync.aligned.m16n8k8.row.col.f32.tf32.tf32.f32 "
        "{%0,%1,%2,%3},{%4,%5,%6,%7},{%8,%9},{%0,%1,%2,%3};"
        : "+f"(c[0]), "+f"(c[1]), "+f"(c[2]), "+f"(c[3])
        : "r"(a[0]), "r"(a[1]), "r"(a[2]), "r"(a[3]), "r"(b[0]), "r"(b[1]));
}
__device__ __forceinline__ void mma_bf16(float* c, const u32* a, const u32* b) {
    asm("mma.sync.aligned.m16n8k16.row.col.f32.bf16.bf16.f32 "
        "{%0,%1,%2,%3},{%4,%5,%6,%7},{%8,%9},{%0,%1,%2,%3};"
        : "+f"(c[0]), "+f"(c[1]), "+f"(c[2]), "+f"(c[3])
        : "r"(a[0]), "r"(a[1]), "r"(a[2]), "r"(a[3]), "r"(b[0]), "r"(b[1]));
}
__device__ __forceinline__ void cp16(void* dst_smem, const void* src) {
    u32 d = (u32)__cvta_generic_to_shared(dst_smem);
    asm volatile("cp.async.cg.shared.global [%0], [%1], 16;" :: "r"(d), "l"(src));
}

// ---------------- bias sum + per-launch barrier reset ----------------
__global__ void bias_sum_kernel(const float* __restrict__ b_ih, const float* __restrict__ b_hh) {
    int i = blockIdx.x * 256 + threadIdx.x;
    if (i < G4H) g_bsum[i] = b_ih[i] + b_hh[i];
    if (i < 2) {
        g_barcA[i] = 0; g_bargA[i] = 0;
        g_barcB[i] = 0; g_bargB[i] = 0;
    }
}

// ---------------- tf32 pre-convert (vectorized) ----------------
__global__ __launch_bounds__(256) void cvt_tf32(const float4* __restrict__ src,
                                                float4* __restrict__ dst, int n4) {
    int i = blockIdx.x * 256 + threadIdx.x;
    if (i < n4) {
        float4 v = src[i];
        dst[i] = make_float4(totf32(v.x), totf32(v.y), totf32(v.z), totf32(v.w));
    }
}

// ---------------- xW repack: [m=b*256+t][col] -> fragment layout --------------
__global__ __launch_bounds__(256) void repack_xw() {
    __shared__ float sm[128 * 68];
    const int ug = blockIdx.x;      // 0..31
    const int t  = blockIdx.y;      // 0..255
    const int tid = threadIdx.x;

#pragma unroll
    for (int p = 0; p < 8; p++) {
        const int i = tid + p * 256;
        const int b = i >> 4, rem = i & 15;
        const int gate = rem >> 2, du4 = rem & 3;
        float4 v = *(const float4*)&g_xW[((size_t)b * SDEC + t) * G4H +
                                         gate * HDIM + ug * 16 + du4 * 4];
        *(float4*)&sm[b * 68 + gate * 16 + du4 * 4] = v;
    }
    __syncthreads();

#pragma unroll
    for (int p = 0; p < 8; p++) {
        const int e4 = tid + p * 256;
        const int blkSel = e4 >> 9;
        const int nbL = blkSel >> 1, mh = blkSel & 1;
        const int ew = e4 & 511;
        const int w = ew >> 6, ni = (ew >> 5) & 1, lane = ew & 31;
        const int gq = lane >> 2, tg = lane & 3;
        const int blk = (2 * ug + nbL) * 2 + mh;
        float v[4];
#pragma unroll
        for (int j = 0; j < 4; j++) {
            const int b = mh * 64 + (w & 3) * 16 + (j >> 1) * 8 + gq;
            const int gate = (tg & 1) * 2 + (j & 1);
            const int du = nbL * 8 + (w >> 2) * 4 + ni * 2 + (tg >> 1);
            v[j] = sm[b * 68 + gate * 16 + du];
        }
        *(float4*)&g_xWf[(((size_t)t * 128 + blk) * 16 + w * 2 + ni) * 128 + lane * 4] =
            make_float4(v[0], v[1], v[2], v[3]);
    }
}

// ================= NT GEMM, pre-converted tf32 inputs, cp.async staging ======
#define KTILE 16
__global__ __launch_bounds__(256) void gemm_nt_pre(
    const float* __restrict__ A, const float* __restrict__ B,
    const float* __restrict__ bias, float* __restrict__ C,
    int M, int N, int K, float alpha,
    size_t sA, size_t sB, size_t sC, int outtf)
{
    __shared__ float As[2][128][20];
    __shared__ float Bs[2][128][20];

    const int z = blockIdx.z;
    A += (size_t)z * sA; B += (size_t)z * sB; C += (size_t)z * sC;

    const int tid = threadIdx.x;
    const int m0 = blockIdx.y * 128, n0 = blockIdx.x * 128;
    const int w = tid >> 5, lane = tid & 31;
    const int wm = (w >> 2) * 64, wn = (w & 3) * 32;
    const int gq = lane >> 2, tg = lane & 3;

    const int lm = tid & 127;
    const int lk = (tid >> 7) * 8;
    const float* Ag = A + (size_t)(m0 + lm) * K + lk;
    const float* Bg = B + (size_t)(n0 + lm) * K + lk;

    float acc[16][4];
#pragma unroll
    for (int i = 0; i < 16; i++)
#pragma unroll
        for (int j = 0; j < 4; j++) acc[i][j] = 0.f;

    cp16(&As[0][lm][lk],     Ag);
    cp16(&As[0][lm][lk + 4], Ag + 4);
    cp16(&Bs[0][lm][lk],     Bg);
    cp16(&Bs[0][lm][lk + 4], Bg + 4);
    asm volatile("cp.async.commit_group;");

    const int KTiles = K / KTILE;
    for (int kt = 0; kt < KTiles; kt++) {
        const int cur = kt & 1;
        const bool has = (kt + 1 < KTiles);
        if (has) {
            const int nb = cur ^ 1;
            cp16(&As[nb][lm][lk],     Ag + (kt + 1) * KTILE);
            cp16(&As[nb][lm][lk + 4], Ag + (kt + 1) * KTILE + 4);
            cp16(&Bs[nb][lm][lk],     Bg + (kt + 1) * KTILE);
            cp16(&Bs[nb][lm][lk + 4], Bg + (kt + 1) * KTILE + 4);
            asm volatile("cp.async.commit_group;");
            asm volatile("cp.async.wait_group 1;");
        } else {
            asm volatile("cp.async.wait_group 0;");
        }
        __syncthreads();
#pragma unroll
        for (int kk = 0; kk < 2; kk++) {
            const int kb = kk * 8;
            u32 af[4][4], bf[4][2];
#pragma unroll
            for (int mi = 0; mi < 4; mi++) {
                af[mi][0] = __float_as_uint(As[cur][wm + mi * 16 + gq    ][kb + tg]);
                af[mi][1] = __float_as_uint(As[cur][wm + mi * 16 + gq + 8][kb + tg]);
                af[mi][2] = __float_as_uint(As[cur][wm + mi * 16 + gq    ][kb + tg + 4]);
                af[mi][3] = __float_as_uint(As[cur][wm + mi * 16 + gq + 8][kb + tg + 4]);
            }
#pragma unroll
            for (int ni = 0; ni < 4; ni++) {
                bf[ni][0] = __float_as_uint(Bs[cur][wn + ni * 8 + gq][kb + tg]);
                bf[ni][1] = __float_as_uint(Bs[cur][wn + ni * 8 + gq][kb + tg + 4]);
            }
#pragma unroll
            for (int mi = 0; mi < 4; mi++)
#pragma unroll
                for (int ni = 0; ni < 4; ni++)
                    mma_tf32(acc[mi * 4 + ni], af[mi], bf[ni]);
        }
        __syncthreads();
    }

#pragma unroll
    for (int ni = 0; ni < 4; ni++) {
        const int ncol = n0 + wn + ni * 8 + tg * 2;
        float2 bv = make_float2(0.f, 0.f);
        if (bias) bv = *(const float2*)&bias[ncol];
#pragma unroll
        for (int mi = 0; mi < 4; mi++) {
            const float* c = acc[mi * 4 + ni];
            const int mr0 = m0 + wm + mi * 16 + gq;
            float2 lo = make_float2(alpha * c[0] + bv.x, alpha * c[1] + bv.y);
            float2 hi = make_float2(alpha * c[2] + bv.x, alpha * c[3] + bv.y);
            if (outtf) {
                lo.x = totf32(lo.x); lo.y = totf32(lo.y);
                hi.x = totf32(hi.x); hi.y = totf32(hi.y);
            }
            *(float2*)&C[(size_t)mr0 * N + ncol]       = lo;
            *(float2*)&C[(size_t)(mr0 + 8) * N + ncol] = hi;
        }
    }
}

// ================= NN GEMM + E add, pre-converted inputs =====================
__global__ __launch_bounds__(256) void gemm_nn_pre(
    const float* __restrict__ A, const float* __restrict__ B,
    const float* __restrict__ E, float* __restrict__ C,
    int M, int N, int K,
    size_t sA, size_t sB, size_t sE, size_t sC, int outtf)
{
    __shared__ float As[2][128][20];
    __shared__ float Bsn[2][16][136];

    const int z = blockIdx.z;
    A += (size_t)z * sA; B += (size_t)z * sB; E += (size_t)z * sE; C += (size_t)z * sC;

    const int tid = threadIdx.x;
    const int m0 = blockIdx.y * 128, n0 = blockIdx.x * 128;
    const int w = tid >> 5, lane = tid & 31;
    const int wm = (w >> 2) * 64, wn = (w & 3) * 32;
    const int gq = lane >> 2, tg = lane & 3;

    const int lm = tid & 127;
    const int lk = (tid >> 7) * 8;
    const float* Ag = A + (size_t)(m0 + lm) * K + lk;
    const int ln  = lane * 4;
    const int lkb = w;
    const float* Bg = B + (size_t)lkb * N + n0 + ln;

    float acc[16][4];
#pragma unroll
    for (int i = 0; i < 16; i++)
#pragma unroll
        for (int j = 0; j < 4; j++) acc[i][j] = 0.f;

    cp16(&As[0][lm][lk],      Ag);
    cp16(&As[0][lm][lk + 4],  Ag + 4);
    cp16(&Bsn[0][lkb][ln],     Bg);
    cp16(&Bsn[0][lkb + 8][ln], Bg + (size_t)8 * N);
    asm volatile("cp.async.commit_group;");

    const int KTiles = K / KTILE;
    for (int kt = 0; kt < KTiles; kt++) {
        const int cur = kt & 1;
        const bool has = (kt + 1 < KTiles);
        if (has) {
            const int nb = cur ^ 1;
            cp16(&As[nb][lm][lk],      Ag + (kt + 1) * KTILE);
            cp16(&As[nb][lm][lk + 4],  Ag + (kt + 1) * KTILE + 4);
            cp16(&Bsn[nb][lkb][ln],     Bg + (size_t)((kt + 1) * KTILE) * N);
            cp16(&Bsn[nb][lkb + 8][ln], Bg + (size_t)((kt + 1) * KTILE + 8) * N);
            asm volatile("cp.async.commit_group;");
            asm volatile("cp.async.wait_group 1;");
        } else {
            asm volatile("cp.async.wait_group 0;");
        }
        __syncthreads();
#pragma unroll
        for (int kk = 0; kk < 2; kk++) {
            const int kb = kk * 8;
            u32 af[4][4], bf[4][2];
#pragma unroll
            for (int mi = 0; mi < 4; mi++) {
                af[mi][0] = __float_as_uint(As[cur][wm + mi * 16 + gq    ][kb + tg]);
                af[mi][1] = __float_as_uint(As[cur][wm + mi * 16 + gq + 8][kb + tg]);
                af[mi][2] = __float_as_uint(As[cur][wm + mi * 16 + gq    ][kb + tg + 4]);
                af[mi][3] = __float_as_uint(As[cur][wm + mi * 16 + gq + 8][kb + tg + 4]);
            }
#pragma unroll
            for (int ni = 0; ni < 4; ni++) {
                bf[ni][0] = __float_as_uint(Bsn[cur][kb + tg    ][wn + ni * 8 + gq]);
                bf[ni][1] = __float_as_uint(Bsn[cur][kb + tg + 4][wn + ni * 8 + gq]);
            }
#pragma unroll
            for (int mi = 0; mi < 4; mi++)
#pragma unroll
                for (int ni = 0; ni < 4; ni++)
                    mma_tf32(acc[mi * 4 + ni], af[mi], bf[ni]);
        }
        __syncthreads();
    }

#pragma unroll
    for (int ni = 0; ni < 4; ni++) {
        const int ncol = n0 + wn + ni * 8 + tg * 2;
#pragma unroll
        for (int mi = 0; mi < 4; mi++) {
            const float* c = acc[mi * 4 + ni];
            const int mr0 = m0 + wm + mi * 16 + gq;
            float2 e0 = *(const float2*)&E[(size_t)mr0 * N + ncol];
            float2 e1 = *(const float2*)&E[(size_t)(mr0 + 8) * N + ncol];
            float2 lo = make_float2(c[0] + e0.x, c[1] + e0.y);
            float2 hi = make_float2(c[2] + e1.x, c[3] + e1.y);
            if (outtf) {
                lo.x = totf32(lo.x); lo.y = totf32(lo.y);
                hi.x = totf32(hi.x); hi.y = totf32(hi.y);
            }
            *(float2*)&C[(size_t)mr0 * N + ncol]       = lo;
            *(float2*)&C[(size_t)(mr0 + 8) * N + ncol] = hi;
        }
    }
}

// ================= persistent bf16 LSTM with split producer barriers =========
#define AH2_STRIDE 72
#define WS2_STRIDE 264
#define SM2_BYTES ((256 * AH2_STRIDE + 32 * WS2_STRIDE) * 4)
__global__ __launch_bounds__(256, 1) void lstm_bf16(const float* __restrict__ W_hh)
{
    extern __shared__ u32 smu[];
    u32* Ah = smu;
    u32* Ws = smu + 256 * AH2_STRIDE;

    const int tid = threadIdx.x;
    const int lane = tid & 31, w = tid >> 5;
    const int gq = lane >> 2, tg = lane & 3;
    const int mt = w & 3, nh = w >> 2;
    const int mh = blockIdx.x & 1, nb = blockIdx.x >> 1;
    const int u0 = nb * 8;
    const int mrow0 = mh * 64 + mt * 16;

    for (int i = tid; i < 32 * 128; i += 256) {
        const int j = i >> 7, f4 = i & 127;
        const int unit = u0 + (j >> 2), gate = j & 3;
        float4 wv = *(const float4*)(W_hh + (size_t)(gate * HDIM + unit) * HDIM + f4 * 4);
        const int kb = f4 >> 2;
        const int p0 = (f4 * 2) & 7, p1 = p0 + 1;
        Ws[j * WS2_STRIDE + kb * 8 + ((p0 & 3) * 2 + (p0 >> 2))] = pack_bf2(wv.x, wv.y);
        Ws[j * WS2_STRIDE + kb * 8 + ((p1 & 3) * 2 + (p1 >> 2))] = pack_bf2(wv.z, wv.w);
    }

    for (int i = tid; i < 4 * 64; i += 256)
        g_hT2[(u0 / 2 + (i >> 6)) * B_ + mh * 64 + (i & 63)] = 0u;

    float cst[2] = {0.f, 0.f};

    // init barrier (relative-gen; ensures h0 + W staging + barrier resets visible)
    __threadfence();
    __syncthreads();
    if (tid == 0) {
        volatile unsigned* genp = &g_barg2[mh];
        unsigned g = *genp;
        if (atomicAdd(&g_barc2[mh], 1) == 63) {
            g_barc2[mh] = 0; __threadfence();
            atomicExch((unsigned*)&g_barg2[mh], g + 1);
        } else { while (*genp == g) { } }
        __threadfence();
    }
    __syncthreads();

    float xg[2][4];
    {
        const float* xb = g_xWf + (((size_t)0 * 128 + blockIdx.x) * 16 + w * 2) * 128;
        float4 xv0 = __ldg((const float4*)(xb + lane * 4));
        float4 xv1 = __ldg((const float4*)(xb + 128 + lane * 4));
        xg[0][0] = xv0.x; xg[0][1] = xv0.y; xg[0][2] = xv0.z; xg[0][3] = xv0.w;
        xg[1][0] = xv1.x; xg[1][1] = xv1.y; xg[1][2] = xv1.z; xg[1][3] = xv1.w;
    }

    for (int t = 0; t < SDEC; t++) {
        const int cur = t & 1, nxt = cur ^ 1;
        const u32* src = g_hT2 + cur * (256 * B_) + mh * 64;

        // wait for group-A producers (units 0..255) of h(t)
        if (tid == 0) {
            volatile unsigned* gp = &g_bargA[mh];
            while (*gp < (unsigned)t) { }
            __threadfence();
        }
        __syncthreads();
#pragma unroll
        for (int p = 0; p < 8; p++) {
            const int i = tid + p * 256;
            const int row = i >> 4, seg = (i & 15) * 4;
            cp16(Ah + row * AH2_STRIDE + seg, src + (size_t)row * B_ + seg);
        }
        asm volatile("cp.async.commit_group;");

        // wait for group-B producers (units 256..511)
        if (tid == 0) {
            volatile unsigned* gp = &g_bargB[mh];
            while (*gp < (unsigned)t) { }
            __threadfence();
        }
        __syncthreads();
#pragma unroll
        for (int p = 8; p < 16; p++) {
            const int i = tid + p * 256;
            const int row = i >> 4, seg = (i & 15) * 4;
            cp16(Ah + row * AH2_STRIDE + seg, src + (size_t)row * B_ + seg);
        }
        asm volatile("cp.async.commit_group;");

        asm volatile("cp.async.wait_group 1;");
        __syncthreads();

        float accA[2][4] = {{0,0,0,0},{0,0,0,0}};
        float accB[2][4] = {{0,0,0,0},{0,0,0,0}};
#pragma unroll 4
        for (int kk = 0; kk < 16; kk++) {
            const int r0 = kk * 8;
            u32 af[4];
            af[0] = Ah[(r0 + tg    ) * AH2_STRIDE + mt * 16 + gq];
            af[1] = Ah[(r0 + tg    ) * AH2_STRIDE + mt * 16 + gq + 8];
            af[2] = Ah[(r0 + 4 + tg) * AH2_STRIDE + mt * 16 + gq];
            af[3] = Ah[(r0 + 4 + tg) * AH2_STRIDE + mt * 16 + gq + 8];
            uint2 w0 = *(const uint2*)&Ws[(nh * 16 + gq    ) * WS2_STRIDE + r0 + tg * 2];
            uint2 w1 = *(const uint2*)&Ws[(nh * 16 + 8 + gq) * WS2_STRIDE + r0 + tg * 2];
            u32 bf0[2] = {w0.x, w0.y};
            u32 bf1[2] = {w1.x, w1.y};
            if (kk & 1) { mma_bf16(accB[0], af, bf0); mma_bf16(accB[1], af, bf1); }
            else        { mma_bf16(accA[0], af, bf0); mma_bf16(accA[1], af, bf1); }
        }

        asm volatile("cp.async.wait_group 0;");
        __syncthreads();

#pragma unroll 4
        for (int kk = 16; kk < 32; kk++) {
            const int r0 = kk * 8;
            u32 af[4];
            af[0] = Ah[(r0 + tg    ) * AH2_STRIDE + mt * 16 + gq];
            af[1] = Ah[(r0 + tg    ) * AH2_STRIDE + mt * 16 + gq + 8];
            af[2] = Ah[(r0 + 4 + tg) * AH2_STRIDE + mt * 16 + gq];
            af[3] = Ah[(r0 + 4 + tg) * AH2_STRIDE + mt * 16 + gq + 8];
            uint2 w0 = *(const uint2*)&Ws[(nh * 16 + gq    ) * WS2_STRIDE + r0 + tg * 2];
            uint2 w1 = *(const uint2*)&Ws[(nh * 16 + 8 + gq) * WS2_STRIDE + r0 + tg * 2];
            u32 bf0[2] = {w0.x, w0.y};
            u32 bf1[2] = {w1.x, w1.y};
            if (kk & 1) { mma_bf16(accB[0], af, bf0); mma_bf16(accB[1], af, bf1); }
            else        { mma_bf16(accA[0], af, bf0); mma_bf16(accA[1], af, bf1); }
        }

        float hsv[2];
        int usv[2], bsv[2];
#pragma unroll
        for (int ni = 0; ni < 2; ni++) {
            float v0 = accA[ni][0] + accB[ni][0] + xg[ni][0];
            float v1 = accA[ni][1] + accB[ni][1] + xg[ni][1];
            float v2 = accA[ni][2] + accB[ni][2] + xg[ni][2];
            float v3 = accA[ni][3] + accB[ni][3] + xg[ni][3];
            float r0 = __shfl_xor_sync(0xffffffffu, v0, 1);
            float r1 = __shfl_xor_sync(0xffffffffu, v1, 1);
            float r2 = __shfl_xor_sync(0xffffffffu, v2, 1);
            float r3 = __shfl_xor_sync(0xffffffffu, v3, 1);
            float iv, fv, gv, ov; int b;
            if (tg & 1) { iv = r2; fv = r3; gv = v2; ov = v3; b = mrow0 + gq + 8; }
            else        { iv = v0; fv = v1; gv = r0; ov = r1; b = mrow0 + gq; }
            float c = sigmoidf_(fv) * cst[ni] + sigmoidf_(iv) * tanhf(gv);
            cst[ni] = c;
            float h = sigmoidf_(ov) * tanhf(c);
            const int u = u0 + nh * 4 + ni * 2 + (tg >> 1);
            float hOth = __shfl_xor_sync(0xffffffffu, h, 2);
            if ((tg & 2) == 0)
                g_hT2[nxt * (256 * B_) + (u >> 1) * B_ + b] = pack_bf2(h, hOth);
            hsv[ni] = h; usv[ni] = u; bsv[ni] = b;
        }

        // prefetch xg for t+1
        if (t + 1 < SDEC) {
            const float* xb = g_xWf + (((size_t)(t + 1) * 128 + blockIdx.x) * 16 + w * 2) * 128;
            float4 xv0 = __ldg((const float4*)(xb + lane * 4));
            float4 xv1 = __ldg((const float4*)(xb + 128 + lane * 4));
            xg[0][0] = xv0.x; xg[0][1] = xv0.y; xg[0][2] = xv0.z; xg[0][3] = xv0.w;
            xg[1][0] = xv1.x; xg[1][1] = xv1.y; xg[1][2] = xv1.z; xg[1][3] = xv1.w;
        }

        // publish -> arrive at OWN group barrier; history stores overlap
        __threadfence();
        __syncthreads();
        if (tid == 0) {
            unsigned* cnt = (nb < 32) ? &g_barcA[mh] : &g_barcB[mh];
            unsigned* gen = (nb < 32) ? &g_bargA[mh] : &g_bargB[mh];
            if (atomicAdd(cnt, 1) == 31) {
                *cnt = 0; __threadfence();
                atomicExch(gen, (unsigned)(t + 1));
            }
        }
#pragma unroll
        for (int ni = 0; ni < 2; ni++) {
            const size_t off = ((size_t)bsv[ni] * SDEC + t) * HDIM + usv[ni];
            g_H[off]   = hsv[ni];
            g_Htf[off] = totf32(hsv[ni]);
        }
    }
}

// ---------------- softmax: one warp per row, tf32 probs ----------------
__global__ __launch_bounds__(256) void softmax_warp(float* __restrict__ S) {
    const int warp = threadIdx.x >> 5, lane = threadIdx.x & 31;
    float* p = S + ((size_t)blockIdx.x * 8 + warp) * SENC;
    float4 a = *(const float4*)(p + lane * 8);
    float4 b = *(const float4*)(p + lane * 8 + 4);
    float mx = fmaxf(fmaxf(fmaxf(a.x, a.y), fmaxf(a.z, a.w)),
                     fmaxf(fmaxf(b.x, b.y), fmaxf(b.z, b.w)));
#pragma unroll
    for (int o = 16; o > 0; o >>= 1) mx = fmaxf(mx, __shfl_xor_sync(0xffffffffu, mx, o));
    float e[8];
    e[0] = __expf(a.x - mx); e[1] = __expf(a.y - mx);
    e[2] = __expf(a.z - mx); e[3] = __expf(a.w - mx);
    e[4] = __expf(b.x - mx); e[5] = __expf(b.y - mx);
    e[6] = __expf(b.z - mx); e[7] = __expf(b.w - mx);
    float s = ((e[0] + e[1]) + (e[2] + e[3])) + ((e[4] + e[5]) + (e[6] + e[7]));
#pragma unroll
    for (int o = 16; o > 0; o >>= 1) s += __shfl_xor_sync(0xffffffffu, s, o);
    const float inv = 1.0f / s;
    float4 o0 = make_float4(totf32(e[0] * inv), totf32(e[1] * inv),
                            totf32(e[2] * inv), totf32(e[3] * inv));
    float4 o1 = make_float4(totf32(e[4] * inv), totf32(e[5] * inv),
                            totf32(e[6] * inv), totf32(e[7] * inv));
    *(float4*)(p + lane * 8)     = o0;
    *(float4*)(p + lane * 8 + 4) = o1;
}

// ---------------- host ----------------
extern "C" void kernel_launch(void* const* d_in, const int* in_sizes, int n_in,
                              void* d_out, int out_size) {
    const float* x    = (const float*)d_in[0];
    const float* enc  = (const float*)d_in[1];
    const float* W_ih = (const float*)d_in[2];
    const float* W_hh = (const float*)d_in[3];
    const float* b_ih = (const float*)d_in[4];
    const float* b_hh = (const float*)d_in[5];
    const float* Wq   = (const float*)d_in[6];
    const float* bq   = (const float*)d_in[7];
    const float* Wk   = (const float*)d_in[8];
    const float* bk   = (const float*)d_in[9];
    const float* Wv   = (const float*)d_in[10];
    const float* bv   = (const float*)d_in[11];
    const float* Wfc  = (const float*)d_in[12];
    const float* bfc  = (const float*)d_in[13];
    float* out = (float*)d_out;

    float *p_xW, *p_K, *p_V, *p_H, *p_Htf, *p_Q, *p_HC, *p_S, *p_bsum;
    float *p_xtf, *p_etf, *p_Wih, *p_Wk, *p_Wv, *p_Wq, *p_Wfc;
    cudaGetSymbolAddress((void**)&p_xW,  g_xW);
    cudaGetSymbolAddress((void**)&p_K,   g_K);
    cudaGetSymbolAddress((void**)&p_V,   g_V);
    cudaGetSymbolAddress((void**)&p_H,   g_H);
    cudaGetSymbolAddress((void**)&p_Htf, g_Htf);
    cudaGetSymbolAddress((void**)&p_Q,   g_Q);
    cudaGetSymbolAddress((void**)&p_HC,  g_HC);
    cudaGetSymbolAddress((void**)&p_S,   g_S);
    cudaGetSymbolAddress((void**)&p_bsum,g_bsum);
    cudaGetSymbolAddress((void**)&p_xtf, g_xtf);
    cudaGetSymbolAddress((void**)&p_etf, g_etf);
    cudaGetSymbolAddress((void**)&p_Wih, g_Wihtf);
    cudaGetSymbolAddress((void**)&p_Wk,  g_Wktf);
    cudaGetSymbolAddress((void**)&p_Wv,  g_Wvtf);
    cudaGetSymbolAddress((void**)&p_Wq,  g_Wqtf);
    cudaGetSymbolAddress((void**)&p_Wfc, g_Wfctf);

    const float scale = 1.0f / sqrtf((float)HDIM);

    cudaFuncSetAttribute(lstm_bf16,
                         cudaFuncAttributeMaxDynamicSharedMemorySize, SM2_BYTES);

    bias_sum_kernel<<<G4H / 256, 256>>>(b_ih, b_hh);

    // one-time tf32 pre-conversions (inputs + weights)
    {
        int n4;
        n4 = (B_ * SDEC * IDIM) / 4;
        cvt_tf32<<<(n4 + 255) / 256, 256>>>((const float4*)x, (float4*)p_xtf, n4);
        n4 = (B_ * SENC * HDIM) / 4;
        cvt_tf32<<<(n4 + 255) / 256, 256>>>((const float4*)enc, (float4*)p_etf, n4);
        n4 = (G4H * IDIM) / 4;
        cvt_tf32<<<(n4 + 255) / 256, 256>>>((const float4*)W_ih, (float4*)p_Wih, n4);
        n4 = (HDIM * HDIM) / 4;
        cvt_tf32<<<(n4 + 255) / 256, 256>>>((const float4*)Wk, (float4*)p_Wk, n4);
        cvt_tf32<<<(n4 + 255) / 256, 256>>>((const float4*)Wv, (float4*)p_Wv, n4);
        cvt_tf32<<<(n4 + 255) / 256, 256>>>((const float4*)Wq, (float4*)p_Wq, n4);
        n4 = (ODIM * HDIM) / 4;
        cvt_tf32<<<(n4 + 255) / 256, 256>>>((const float4*)Wfc, (float4*)p_Wfc, n4);
    }

    // xW = x @ W_ih^T + (b_ih+b_hh)   (fp32 out)
    gemm_nt_pre<<<dim3(G4H / 128, MROWS / 128, 1), 256>>>(
        p_xtf, p_Wih, p_bsum, p_xW, MROWS, G4H, IDIM, 1.0f, 0, 0, 0, 0);
    // repack to recurrence fragment layout
    repack_xw<<<dim3(32, 256), 256>>>();
    // K = enc @ Wk^T + bk   (tf32 out)
    gemm_nt_pre<<<dim3(HDIM / 128, MROWS / 128, 1), 256>>>(
        p_etf, p_Wk, bk, p_K, MROWS, HDIM, HDIM, 1.0f, 0, 0, 0, 1);
    // V = K @ Wv^T + bv     (tf32 out)
    gemm_nt_pre<<<dim3(HDIM / 128, MROWS / 128, 1), 256>>>(
        p_K, p_Wv, bv, p_V, MROWS, HDIM, HDIM, 1.0f, 0, 0, 0, 1);

    // entire sequential LSTM in one persistent bf16 tensor-core launch
    lstm_bf16<<<128, 256, SM2_BYTES>>>(W_hh);

    // Q = Htf @ Wq^T + bq   (fast pre-converted path; tf32 out)
    gemm_nt_pre<<<dim3(HDIM / 128, MROWS / 128, 1), 256>>>(
        p_Htf, p_Wq, bq, p_Q, MROWS, HDIM, HDIM, 1.0f, 0, 0, 0, 1);

    // scores: per-batch S[t,s] = scale * Q[t,:]·K[s,:]  (fp32 out -> softmax)
    gemm_nt_pre<<<dim3(SENC / 128, SDEC / 128, B_), 256>>>(
        p_Q, p_K, nullptr, p_S, SDEC, SENC, HDIM, scale,
        (size_t)SDEC * HDIM, (size_t)SENC * HDIM, (size_t)SDEC * SENC, 0);

    softmax_warp<<<(B_ * SDEC) / 8, 256>>>(p_S);

    // context + h: HC = S@V + H  (tf32 out)
    gemm_nn_pre<<<dim3(HDIM / 128, SDEC / 128, B_), 256>>>(
        p_S, p_V, p_H, p_HC, SDEC, HDIM, SENC,
        (size_t)SDEC * SENC, (size_t)SENC * HDIM,
        (size_t)SDEC * HDIM, (size_t)SDEC * HDIM, 1);

    // out = HC @ Wfc^T + bfc  (fp32 final)
    gemm_nt_pre<<<dim3(ODIM / 128, MROWS / 128, 1), 256>>>(
        p_HC, p_Wfc, bfc, out, MROWS, ODIM, HDIM, 1.0f, 0, 0, 0, 0);
}

// round 15
// speedup vs baseline: 1.0490x; 1.0490x over previous
#include <cuda_runtime.h>
#include <math.h>

#define B_    128
#define SDEC  256
#define SENC  256
#define IDIM  256
#define HDIM  512
#define ODIM  256
#define G4H   2048
#define MROWS 32768   // B_*SDEC == B_*SENC

typedef unsigned long long ull;
typedef unsigned int u32;

// ---------------- scratch (device globals; no allocs allowed) ----------------
__device__ float g_xW [(size_t)MROWS * G4H];  // x@W_ih^T + biases, [m=b*256+t][col]
__device__ float g_xWf[(size_t)MROWS * G4H];  // fragment layout [t][blk][w][ni][lane][j]
__device__ float g_K [(size_t)MROWS * HDIM];  // tf32(enc@Wk^T + bk)
__device__ float g_V [(size_t)MROWS * HDIM];  // tf32(K@Wv^T + bv)
__device__ float g_H [(size_t)MROWS * HDIM];  // all h_t fp32 [b*256+t][u]
__device__ float g_Htf[(size_t)MROWS * HDIM]; // tf32(h) for Q projection
__device__ float g_Q [(size_t)MROWS * HDIM];  // tf32(H@Wq^T + bq)
__device__ float g_HC[(size_t)MROWS * HDIM];  // tf32(h + context)
__device__ float g_S [(size_t)B_ * SDEC * SENC]; // scores fp32 -> probs tf32
__device__ u32   g_hT2[2 * (HDIM / 2) * B_];  // h ping-pong bf16x2 pairs
__device__ float g_bsum[G4H];
__device__ float g_xtf [(size_t)B_ * SDEC * IDIM];   // tf32(x)
__device__ float g_etf [(size_t)B_ * SENC * HDIM];   // tf32(enc)
__device__ float g_Wihtf[G4H * IDIM];
__device__ float g_Wktf [HDIM * HDIM];
__device__ float g_Wvtf [HDIM * HDIM];
__device__ float g_Wqtf [HDIM * HDIM];
__device__ float g_Wfctf[ODIM * HDIM];
__device__ unsigned g_barc2[2];   // per-mh barrier (relative-gen, replay-safe)
__device__ unsigned g_barg2[2];

__device__ __forceinline__ float sigmoidf_(float x) { return 1.0f / (1.0f + __expf(-x)); }

__device__ __forceinline__ float totf32(float x) {
    u32 r;
    asm("cvt.rna.tf32.f32 %0, %1;" : "=r"(r) : "f"(x));
    return __uint_as_float(r);
}
__device__ __forceinline__ u32 pack_bf2(float lo, float hi) {
    u32 r;
    asm("cvt.rn.bf16x2.f32 %0, %1, %2;" : "=r"(r) : "f"(hi), "f"(lo));
    return r;
}
__device__ __forceinline__ void mma_tf32(float* c, const u32* a, const u32* b) {
    asm("mma.sync.aligned.m16n8k8.row.col.f32.tf32.tf32.f32 "
        "{%0,%1,%2,%3},{%4,%5,%6,%7},{%8,%9},{%0,%1,%2,%3};"
        : "+f"(c[0]), "+f"(c[1]), "+f"(c[2]), "+f"(c[3])
        : "r"(a[0]), "r"(a[1]), "r"(a[2]), "r"(a[3]), "r"(b[0]), "r"(b[1]));
}
__device__ __forceinline__ void mma_bf16(float* c, const u32* a, const u32* b) {
    asm("mma.sync.aligned.m16n8k16.row.col.f32.bf16.bf16.f32 "
        "{%0,%1,%2,%3},{%4,%5,%6,%7},{%8,%9},{%0,%1,%2,%3};"
        : "+f"(c[0]), "+f"(c[1]), "+f"(c[2]), "+f"(c[3])
        : "r"(a[0]), "r"(a[1]), "r"(a[2]), "r"(a[3]), "r"(b[0]), "r"(b[1]));
}
__device__ __forceinline__ void cp16(void* dst_smem, const void* src) {
    u32 d = (u32)__cvta_generic_to_shared(dst_smem);
    asm volatile("cp.async.cg.shared.global [%0], [%1], 16;" :: "r"(d), "l"(src));
}

// ---------------- bias sum ----------------
__global__ void bias_sum_kernel(const float* __restrict__ b_ih, const float* __restrict__ b_hh) {
    int i = blockIdx.x * 256 + threadIdx.x;
    if (i < G4H) g_bsum[i] = b_ih[i] + b_hh[i];
}

// ---------------- tf32 pre-convert (vectorized) ----------------
__global__ __launch_bounds__(256) void cvt_tf32(const float4* __restrict__ src,
                                                float4* __restrict__ dst, int n4) {
    int i = blockIdx.x * 256 + threadIdx.x;
    if (i < n4) {
        float4 v = src[i];
        dst[i] = make_float4(totf32(v.x), totf32(v.y), totf32(v.z), totf32(v.w));
    }
}

// ---------------- xW repack: [m=b*256+t][col] -> fragment layout --------------
__global__ __launch_bounds__(256) void repack_xw() {
    __shared__ float sm[128 * 68];
    const int ug = blockIdx.x;      // 0..31
    const int t  = blockIdx.y;      // 0..255
    const int tid = threadIdx.x;

#pragma unroll
    for (int p = 0; p < 8; p++) {
        const int i = tid + p * 256;
        const int b = i >> 4, rem = i & 15;
        const int gate = rem >> 2, du4 = rem & 3;
        float4 v = *(const float4*)&g_xW[((size_t)b * SDEC + t) * G4H +
                                         gate * HDIM + ug * 16 + du4 * 4];
        *(float4*)&sm[b * 68 + gate * 16 + du4 * 4] = v;
    }
    __syncthreads();

#pragma unroll
    for (int p = 0; p < 8; p++) {
        const int e4 = tid + p * 256;
        const int blkSel = e4 >> 9;
        const int nbL = blkSel >> 1, mh = blkSel & 1;
        const int ew = e4 & 511;
        const int w = ew >> 6, ni = (ew >> 5) & 1, lane = ew & 31;
        const int gq = lane >> 2, tg = lane & 3;
        const int blk = (2 * ug + nbL) * 2 + mh;
        float v[4];
#pragma unroll
        for (int j = 0; j < 4; j++) {
            const int b = mh * 64 + (w & 3) * 16 + (j >> 1) * 8 + gq;
            const int gate = (tg & 1) * 2 + (j & 1);
            const int du = nbL * 8 + (w >> 2) * 4 + ni * 2 + (tg >> 1);
            v[j] = sm[b * 68 + gate * 16 + du];
        }
        *(float4*)&g_xWf[(((size_t)t * 128 + blk) * 16 + w * 2 + ni) * 128 + lane * 4] =
            make_float4(v[0], v[1], v[2], v[3]);
    }
}

// ================= NT GEMM, pre-converted tf32 inputs, cp.async staging ======
#define KTILE 16
__global__ __launch_bounds__(256) void gemm_nt_pre(
    const float* __restrict__ A, const float* __restrict__ B,
    const float* __restrict__ bias, float* __restrict__ C,
    int M, int N, int K, float alpha,
    size_t sA, size_t sB, size_t sC, int outtf)
{
    __shared__ float As[2][128][20];
    __shared__ float Bs[2][128][20];

    const int z = blockIdx.z;
    A += (size_t)z * sA; B += (size_t)z * sB; C += (size_t)z * sC;

    const int tid = threadIdx.x;
    const int m0 = blockIdx.y * 128, n0 = blockIdx.x * 128;
    const int w = tid >> 5, lane = tid & 31;
    const int wm = (w >> 2) * 64, wn = (w & 3) * 32;
    const int gq = lane >> 2, tg = lane & 3;

    const int lm = tid & 127;
    const int lk = (tid >> 7) * 8;
    const float* Ag = A + (size_t)(m0 + lm) * K + lk;
    const float* Bg = B + (size_t)(n0 + lm) * K + lk;

    float acc[16][4];
#pragma unroll
    for (int i = 0; i < 16; i++)
#pragma unroll
        for (int j = 0; j < 4; j++) acc[i][j] = 0.f;

    cp16(&As[0][lm][lk],     Ag);
    cp16(&As[0][lm][lk + 4], Ag + 4);
    cp16(&Bs[0][lm][lk],     Bg);
    cp16(&Bs[0][lm][lk + 4], Bg + 4);
    asm volatile("cp.async.commit_group;");

    const int KTiles = K / KTILE;
    for (int kt = 0; kt < KTiles; kt++) {
        const int cur = kt & 1;
        const bool has = (kt + 1 < KTiles);
        if (has) {
            const int nb = cur ^ 1;
            cp16(&As[nb][lm][lk],     Ag + (kt + 1) * KTILE);
            cp16(&As[nb][lm][lk + 4], Ag + (kt + 1) * KTILE + 4);
            cp16(&Bs[nb][lm][lk],     Bg + (kt + 1) * KTILE);
            cp16(&Bs[nb][lm][lk + 4], Bg + (kt + 1) * KTILE + 4);
            asm volatile("cp.async.commit_group;");
            asm volatile("cp.async.wait_group 1;");
        } else {
            asm volatile("cp.async.wait_group 0;");
        }
        __syncthreads();
#pragma unroll
        for (int kk = 0; kk < 2; kk++) {
            const int kb = kk * 8;
            u32 af[4][4], bf[4][2];
#pragma unroll
            for (int mi = 0; mi < 4; mi++) {
                af[mi][0] = __float_as_uint(As[cur][wm + mi * 16 + gq    ][kb + tg]);
                af[mi][1] = __float_as_uint(As[cur][wm + mi * 16 + gq + 8][kb + tg]);
                af[mi][2] = __float_as_uint(As[cur][wm + mi * 16 + gq    ][kb + tg + 4]);
                af[mi][3] = __float_as_uint(As[cur][wm + mi * 16 + gq + 8][kb + tg + 4]);
            }
#pragma unroll
            for (int ni = 0; ni < 4; ni++) {
                bf[ni][0] = __float_as_uint(Bs[cur][wn + ni * 8 + gq][kb + tg]);
                bf[ni][1] = __float_as_uint(Bs[cur][wn + ni * 8 + gq][kb + tg + 4]);
            }
#pragma unroll
            for (int mi = 0; mi < 4; mi++)
#pragma unroll
                for (int ni = 0; ni < 4; ni++)
                    mma_tf32(acc[mi * 4 + ni], af[mi], bf[ni]);
        }
        __syncthreads();
    }

#pragma unroll
    for (int ni = 0; ni < 4; ni++) {
        const int ncol = n0 + wn + ni * 8 + tg * 2;
        float2 bv = make_float2(0.f, 0.f);
        if (bias) bv = *(const float2*)&bias[ncol];
#pragma unroll
        for (int mi = 0; mi < 4; mi++) {
            const float* c = acc[mi * 4 + ni];
            const int mr0 = m0 + wm + mi * 16 + gq;
            float2 lo = make_float2(alpha * c[0] + bv.x, alpha * c[1] + bv.y);
            float2 hi = make_float2(alpha * c[2] + bv.x, alpha * c[3] + bv.y);
            if (outtf) {
                lo.x = totf32(lo.x); lo.y = totf32(lo.y);
                hi.x = totf32(hi.x); hi.y = totf32(hi.y);
            }
            *(float2*)&C[(size_t)mr0 * N + ncol]       = lo;
            *(float2*)&C[(size_t)(mr0 + 8) * N + ncol] = hi;
        }
    }
}

// ================= NN GEMM + E add, pre-converted inputs =====================
__global__ __launch_bounds__(256) void gemm_nn_pre(
    const float* __restrict__ A, const float* __restrict__ B,
    const float* __restrict__ E, float* __restrict__ C,
    int M, int N, int K,
    size_t sA, size_t sB, size_t sE, size_t sC, int outtf)
{
    __shared__ float As[2][128][20];
    __shared__ float Bsn[2][16][136];

    const int z = blockIdx.z;
    A += (size_t)z * sA; B += (size_t)z * sB; E += (size_t)z * sE; C += (size_t)z * sC;

    const int tid = threadIdx.x;
    const int m0 = blockIdx.y * 128, n0 = blockIdx.x * 128;
    const int w = tid >> 5, lane = tid & 31;
    const int wm = (w >> 2) * 64, wn = (w & 3) * 32;
    const int gq = lane >> 2, tg = lane & 3;

    const int lm = tid & 127;
    const int lk = (tid >> 7) * 8;
    const float* Ag = A + (size_t)(m0 + lm) * K + lk;
    const int ln  = lane * 4;
    const int lkb = w;
    const float* Bg = B + (size_t)lkb * N + n0 + ln;

    float acc[16][4];
#pragma unroll
    for (int i = 0; i < 16; i++)
#pragma unroll
        for (int j = 0; j < 4; j++) acc[i][j] = 0.f;

    cp16(&As[0][lm][lk],      Ag);
    cp16(&As[0][lm][lk + 4],  Ag + 4);
    cp16(&Bsn[0][lkb][ln],     Bg);
    cp16(&Bsn[0][lkb + 8][ln], Bg + (size_t)8 * N);
    asm volatile("cp.async.commit_group;");

    const int KTiles = K / KTILE;
    for (int kt = 0; kt < KTiles; kt++) {
        const int cur = kt & 1;
        const bool has = (kt + 1 < KTiles);
        if (has) {
            const int nb = cur ^ 1;
            cp16(&As[nb][lm][lk],      Ag + (kt + 1) * KTILE);
            cp16(&As[nb][lm][lk + 4],  Ag + (kt + 1) * KTILE + 4);
            cp16(&Bsn[nb][lkb][ln],     Bg + (size_t)((kt + 1) * KTILE) * N);
            cp16(&Bsn[nb][lkb + 8][ln], Bg + (size_t)((kt + 1) * KTILE + 8) * N);
            asm volatile("cp.async.commit_group;");
            asm volatile("cp.async.wait_group 1;");
        } else {
            asm volatile("cp.async.wait_group 0;");
        }
        __syncthreads();
#pragma unroll
        for (int kk = 0; kk < 2; kk++) {
            const int kb = kk * 8;
            u32 af[4][4], bf[4][2];
#pragma unroll
            for (int mi = 0; mi < 4; mi++) {
                af[mi][0] = __float_as_uint(As[cur][wm + mi * 16 + gq    ][kb + tg]);
                af[mi][1] = __float_as_uint(As[cur][wm + mi * 16 + gq + 8][kb + tg]);
                af[mi][2] = __float_as_uint(As[cur][wm + mi * 16 + gq    ][kb + tg + 4]);
                af[mi][3] = __float_as_uint(As[cur][wm + mi * 16 + gq + 8][kb + tg + 4]);
            }
#pragma unroll
            for (int ni = 0; ni < 4; ni++) {
                bf[ni][0] = __float_as_uint(Bsn[cur][kb + tg    ][wn + ni * 8 + gq]);
                bf[ni][1] = __float_as_uint(Bsn[cur][kb + tg + 4][wn + ni * 8 + gq]);
            }
#pragma unroll
            for (int mi = 0; mi < 4; mi++)
#pragma unroll
                for (int ni = 0; ni < 4; ni++)
                    mma_tf32(acc[mi * 4 + ni], af[mi], bf[ni]);
        }
        __syncthreads();
    }

#pragma unroll
    for (int ni = 0; ni < 4; ni++) {
        const int ncol = n0 + wn + ni * 8 + tg * 2;
#pragma unroll
        for (int mi = 0; mi < 4; mi++) {
            const float* c = acc[mi * 4 + ni];
            const int mr0 = m0 + wm + mi * 16 + gq;
            float2 e0 = *(const float2*)&E[(size_t)mr0 * N + ncol];
            float2 e1 = *(const float2*)&E[(size_t)(mr0 + 8) * N + ncol];
            float2 lo = make_float2(c[0] + e0.x, c[1] + e0.y);
            float2 hi = make_float2(c[2] + e1.x, c[3] + e1.y);
            if (outtf) {
                lo.x = totf32(lo.x); lo.y = totf32(lo.y);
                hi.x = totf32(hi.x); hi.y = totf32(hi.y);
            }
            *(float2*)&C[(size_t)mr0 * N + ncol]       = lo;
            *(float2*)&C[(size_t)(mr0 + 8) * N + ncol] = hi;
        }
    }
}

// ================= persistent bf16 LSTM (single per-mh barrier, R12 style) ===
#define AH2_STRIDE 72
#define WS2_STRIDE 264
#define SM2_BYTES ((256 * AH2_STRIDE + 32 * WS2_STRIDE) * 4)
__global__ __launch_bounds__(256, 1) void lstm_bf16(const float* __restrict__ W_hh)
{
    extern __shared__ u32 smu[];
    u32* Ah = smu;
    u32* Ws = smu + 256 * AH2_STRIDE;

    const int tid = threadIdx.x;
    const int lane = tid & 31, w = tid >> 5;
    const int gq = lane >> 2, tg = lane & 3;
    const int mt = w & 3, nh = w >> 2;
    const int mh = blockIdx.x & 1, nb = blockIdx.x >> 1;
    const int u0 = nb * 8;
    const int mrow0 = mh * 64 + mt * 16;

    for (int i = tid; i < 32 * 128; i += 256) {
        const int j = i >> 7, f4 = i & 127;
        const int unit = u0 + (j >> 2), gate = j & 3;
        float4 wv = *(const float4*)(W_hh + (size_t)(gate * HDIM + unit) * HDIM + f4 * 4);
        const int kb = f4 >> 2;
        const int p0 = (f4 * 2) & 7, p1 = p0 + 1;
        Ws[j * WS2_STRIDE + kb * 8 + ((p0 & 3) * 2 + (p0 >> 2))] = pack_bf2(wv.x, wv.y);
        Ws[j * WS2_STRIDE + kb * 8 + ((p1 & 3) * 2 + (p1 >> 2))] = pack_bf2(wv.z, wv.w);
    }

    for (int i = tid; i < 4 * 64; i += 256)
        g_hT2[(u0 / 2 + (i >> 6)) * B_ + mh * 64 + (i & 63)] = 0u;

    float cst[2] = {0.f, 0.f};

    __threadfence();
    __syncthreads();
    if (tid == 0) {
        volatile unsigned* genp = &g_barg2[mh];
        unsigned g = *genp;
        if (atomicAdd(&g_barc2[mh], 1) == 63) {
            g_barc2[mh] = 0; __threadfence();
            atomicExch((unsigned*)&g_barg2[mh], g + 1);
        } else { while (*genp == g) { } }
        __threadfence();
    }
    __syncthreads();

    float xg[2][4];
    {
        const float* xb = g_xWf + (((size_t)0 * 128 + blockIdx.x) * 16 + w * 2) * 128;
        float4 xv0 = __ldg((const float4*)(xb + lane * 4));
        float4 xv1 = __ldg((const float4*)(xb + 128 + lane * 4));
        xg[0][0] = xv0.x; xg[0][1] = xv0.y; xg[0][2] = xv0.z; xg[0][3] = xv0.w;
        xg[1][0] = xv1.x; xg[1][1] = xv1.y; xg[1][2] = xv1.z; xg[1][3] = xv1.w;
    }

    for (int t = 0; t < SDEC; t++) {
        const int cur = t & 1, nxt = cur ^ 1;

        const u32* src = g_hT2 + cur * (256 * B_) + mh * 64;
        {
#pragma unroll
            for (int p = 0; p < 8; p++) {
                const int i = tid + p * 256;
                const int row = i >> 4, seg = (i & 15) * 4;
                cp16(Ah + row * AH2_STRIDE + seg, src + (size_t)row * B_ + seg);
            }
            asm volatile("cp.async.commit_group;");
#pragma unroll
            for (int p = 8; p < 16; p++) {
                const int i = tid + p * 256;
                const int row = i >> 4, seg = (i & 15) * 4;
                cp16(Ah + row * AH2_STRIDE + seg, src + (size_t)row * B_ + seg);
            }
            asm volatile("cp.async.commit_group;");
        }

        asm volatile("cp.async.wait_group 1;");
        __syncthreads();

        float accA[2][4] = {{0,0,0,0},{0,0,0,0}};
        float accB[2][4] = {{0,0,0,0},{0,0,0,0}};
#pragma unroll 4
        for (int kk = 0; kk < 16; kk++) {
            const int r0 = kk * 8;
            u32 af[4];
            af[0] = Ah[(r0 + tg    ) * AH2_STRIDE + mt * 16 + gq];
            af[1] = Ah[(r0 + tg    ) * AH2_STRIDE + mt * 16 + gq + 8];
            af[2] = Ah[(r0 + 4 + tg) * AH2_STRIDE + mt * 16 + gq];
            af[3] = Ah[(r0 + 4 + tg) * AH2_STRIDE + mt * 16 + gq + 8];
            uint2 w0 = *(const uint2*)&Ws[(nh * 16 + gq    ) * WS2_STRIDE + r0 + tg * 2];
            uint2 w1 = *(const uint2*)&Ws[(nh * 16 + 8 + gq) * WS2_STRIDE + r0 + tg * 2];
            u32 bf0[2] = {w0.x, w0.y};
            u32 bf1[2] = {w1.x, w1.y};
            if (kk & 1) { mma_bf16(accB[0], af, bf0); mma_bf16(accB[1], af, bf1); }
            else        { mma_bf16(accA[0], af, bf0); mma_bf16(accA[1], af, bf1); }
        }

        asm volatile("cp.async.wait_group 0;");
        __syncthreads();

#pragma unroll 4
        for (int kk = 16; kk < 32; kk++) {
            const int r0 = kk * 8;
            u32 af[4];
            af[0] = Ah[(r0 + tg    ) * AH2_STRIDE + mt * 16 + gq];
            af[1] = Ah[(r0 + tg    ) * AH2_STRIDE + mt * 16 + gq + 8];
            af[2] = Ah[(r0 + 4 + tg) * AH2_STRIDE + mt * 16 + gq];
            af[3] = Ah[(r0 + 4 + tg) * AH2_STRIDE + mt * 16 + gq + 8];
            uint2 w0 = *(const uint2*)&Ws[(nh * 16 + gq    ) * WS2_STRIDE + r0 + tg * 2];
            uint2 w1 = *(const uint2*)&Ws[(nh * 16 + 8 + gq) * WS2_STRIDE + r0 + tg * 2];
            u32 bf0[2] = {w0.x, w0.y};
            u32 bf1[2] = {w1.x, w1.y};
            if (kk & 1) { mma_bf16(accB[0], af, bf0); mma_bf16(accB[1], af, bf1); }
            else        { mma_bf16(accA[0], af, bf0); mma_bf16(accA[1], af, bf1); }
        }

        float hsv[2];
        int usv[2], bsv[2];
#pragma unroll
        for (int ni = 0; ni < 2; ni++) {
            float v0 = accA[ni][0] + accB[ni][0] + xg[ni][0];
            float v1 = accA[ni][1] + accB[ni][1] + xg[ni][1];
            float v2 = accA[ni][2] + accB[ni][2] + xg[ni][2];
            float v3 = accA[ni][3] + accB[ni][3] + xg[ni][3];
            float r0 = __shfl_xor_sync(0xffffffffu, v0, 1);
            float r1 = __shfl_xor_sync(0xffffffffu, v1, 1);
            float r2 = __shfl_xor_sync(0xffffffffu, v2, 1);
            float r3 = __shfl_xor_sync(0xffffffffu, v3, 1);
            float iv, fv, gv, ov; int b;
            if (tg & 1) { iv = r2; fv = r3; gv = v2; ov = v3; b = mrow0 + gq + 8; }
            else        { iv = v0; fv = v1; gv = r0; ov = r1; b = mrow0 + gq; }
            float c = sigmoidf_(fv) * cst[ni] + sigmoidf_(iv) * tanhf(gv);
            cst[ni] = c;
            float h = sigmoidf_(ov) * tanhf(c);
            const int u = u0 + nh * 4 + ni * 2 + (tg >> 1);
            float hOth = __shfl_xor_sync(0xffffffffu, h, 2);
            if ((tg & 2) == 0)
                g_hT2[nxt * (256 * B_) + (u >> 1) * B_ + b] = pack_bf2(h, hOth);
            hsv[ni] = h; usv[ni] = u; bsv[ni] = b;
        }

        // prefetch xg for t+1 (consumed after barrier; hides LDG latency)
        if (t + 1 < SDEC) {
            const float* xb = g_xWf + (((size_t)(t + 1) * 128 + blockIdx.x) * 16 + w * 2) * 128;
            float4 xv0 = __ldg((const float4*)(xb + lane * 4));
            float4 xv1 = __ldg((const float4*)(xb + 128 + lane * 4));
            xg[0][0] = xv0.x; xg[0][1] = xv0.y; xg[0][2] = xv0.z; xg[0][3] = xv0.w;
            xg[1][0] = xv1.x; xg[1][1] = xv1.y; xg[1][2] = xv1.z; xg[1][3] = xv1.w;
        }

        // publish, arrive (per-mh), overlap history stores with the wait
        __threadfence();
        __syncthreads();
        unsigned mygen = 0; bool rel = false;
        if (tid == 0) {
            volatile unsigned* genp = &g_barg2[mh];
            mygen = *genp;
            if (atomicAdd(&g_barc2[mh], 1) == 63) {
                g_barc2[mh] = 0; __threadfence();
                atomicExch((unsigned*)&g_barg2[mh], mygen + 1);
                rel = true;
            }
        }
#pragma unroll
        for (int ni = 0; ni < 2; ni++) {
            const size_t off = ((size_t)bsv[ni] * SDEC + t) * HDIM + usv[ni];
            g_H[off]   = hsv[ni];
            g_Htf[off] = totf32(hsv[ni]);
        }
        if (tid == 0 && !rel) {
            volatile unsigned* genp = &g_barg2[mh];
            while (*genp == mygen) { }
            __threadfence();
        }
        __syncthreads();
    }
}

// ---------------- softmax: one warp per row, tf32 probs ----------------
__global__ __launch_bounds__(256) void softmax_warp(float* __restrict__ S) {
    const int warp = threadIdx.x >> 5, lane = threadIdx.x & 31;
    float* p = S + ((size_t)blockIdx.x * 8 + warp) * SENC;
    float4 a = *(const float4*)(p + lane * 8);
    float4 b = *(const float4*)(p + lane * 8 + 4);
    float mx = fmaxf(fmaxf(fmaxf(a.x, a.y), fmaxf(a.z, a.w)),
                     fmaxf(fmaxf(b.x, b.y), fmaxf(b.z, b.w)));
#pragma unroll
    for (int o = 16; o > 0; o >>= 1) mx = fmaxf(mx, __shfl_xor_sync(0xffffffffu, mx, o));
    float e[8];
    e[0] = __expf(a.x - mx); e[1] = __expf(a.y - mx);
    e[2] = __expf(a.z - mx); e[3] = __expf(a.w - mx);
    e[4] = __expf(b.x - mx); e[5] = __expf(b.y - mx);
    e[6] = __expf(b.z - mx); e[7] = __expf(b.w - mx);
    float s = ((e[0] + e[1]) + (e[2] + e[3])) + ((e[4] + e[5]) + (e[6] + e[7]));
#pragma unroll
    for (int o = 16; o > 0; o >>= 1) s += __shfl_xor_sync(0xffffffffu, s, o);
    const float inv = 1.0f / s;
    float4 o0 = make_float4(totf32(e[0] * inv), totf32(e[1] * inv),
                            totf32(e[2] * inv), totf32(e[3] * inv));
    float4 o1 = make_float4(totf32(e[4] * inv), totf32(e[5] * inv),
                            totf32(e[6] * inv), totf32(e[7] * inv));
    *(float4*)(p + lane * 8)     = o0;
    *(float4*)(p + lane * 8 + 4) = o1;
}

// ---------------- host ----------------
extern "C" void kernel_launch(void* const* d_in, const int* in_sizes, int n_in,
                              void* d_out, int out_size) {
    const float* x    = (const float*)d_in[0];
    const float* enc  = (const float*)d_in[1];
    const float* W_ih = (const float*)d_in[2];
    const float* W_hh = (const float*)d_in[3];
    const float* b_ih = (const float*)d_in[4];
    const float* b_hh = (const float*)d_in[5];
    const float* Wq   = (const float*)d_in[6];
    const float* bq   = (const float*)d_in[7];
    const float* Wk   = (const float*)d_in[8];
    const float* bk   = (const float*)d_in[9];
    const float* Wv   = (const float*)d_in[10];
    const float* bv   = (const float*)d_in[11];
    const float* Wfc  = (const float*)d_in[12];
    const float* bfc  = (const float*)d_in[13];
    float* out = (float*)d_out;

    float *p_xW, *p_K, *p_V, *p_H, *p_Htf, *p_Q, *p_HC, *p_S, *p_bsum;
    float *p_xtf, *p_etf, *p_Wih, *p_Wk, *p_Wv, *p_Wq, *p_Wfc;
    cudaGetSymbolAddress((void**)&p_xW,  g_xW);
    cudaGetSymbolAddress((void**)&p_K,   g_K);
    cudaGetSymbolAddress((void**)&p_V,   g_V);
    cudaGetSymbolAddress((void**)&p_H,   g_H);
    cudaGetSymbolAddress((void**)&p_Htf, g_Htf);
    cudaGetSymbolAddress((void**)&p_Q,   g_Q);
    cudaGetSymbolAddress((void**)&p_HC,  g_HC);
    cudaGetSymbolAddress((void**)&p_S,   g_S);
    cudaGetSymbolAddress((void**)&p_bsum,g_bsum);
    cudaGetSymbolAddress((void**)&p_xtf, g_xtf);
    cudaGetSymbolAddress((void**)&p_etf, g_etf);
    cudaGetSymbolAddress((void**)&p_Wih, g_Wihtf);
    cudaGetSymbolAddress((void**)&p_Wk,  g_Wktf);
    cudaGetSymbolAddress((void**)&p_Wv,  g_Wvtf);
    cudaGetSymbolAddress((void**)&p_Wq,  g_Wqtf);
    cudaGetSymbolAddress((void**)&p_Wfc, g_Wfctf);

    const float scale = 1.0f / sqrtf((float)HDIM);

    cudaFuncSetAttribute(lstm_bf16,
                         cudaFuncAttributeMaxDynamicSharedMemorySize, SM2_BYTES);

    bias_sum_kernel<<<G4H / 256, 256>>>(b_ih, b_hh);

    // one-time tf32 pre-conversions (inputs + weights)
    {
        int n4;
        n4 = (B_ * SDEC * IDIM) / 4;
        cvt_tf32<<<(n4 + 255) / 256, 256>>>((const float4*)x, (float4*)p_xtf, n4);
        n4 = (B_ * SENC * HDIM) / 4;
        cvt_tf32<<<(n4 + 255) / 256, 256>>>((const float4*)enc, (float4*)p_etf, n4);
        n4 = (G4H * IDIM) / 4;
        cvt_tf32<<<(n4 + 255) / 256, 256>>>((const float4*)W_ih, (float4*)p_Wih, n4);
        n4 = (HDIM * HDIM) / 4;
        cvt_tf32<<<(n4 + 255) / 256, 256>>>((const float4*)Wk, (float4*)p_Wk, n4);
        cvt_tf32<<<(n4 + 255) / 256, 256>>>((const float4*)Wv, (float4*)p_Wv, n4);
        cvt_tf32<<<(n4 + 255) / 256, 256>>>((const float4*)Wq, (float4*)p_Wq, n4);
        n4 = (ODIM * HDIM) / 4;
        cvt_tf32<<<(n4 + 255) / 256, 256>>>((const float4*)Wfc, (float4*)p_Wfc, n4);
    }

    // xW = x @ W_ih^T + (b_ih+b_hh)   (fp32 out)
    gemm_nt_pre<<<dim3(G4H / 128, MROWS / 128, 1), 256>>>(
        p_xtf, p_Wih, p_bsum, p_xW, MROWS, G4H, IDIM, 1.0f, 0, 0, 0, 0);
    // repack to recurrence fragment layout
    repack_xw<<<dim3(32, 256), 256>>>();
    // K = enc @ Wk^T + bk   (tf32 out)
    gemm_nt_pre<<<dim3(HDIM / 128, MROWS / 128, 1), 256>>>(
        p_etf, p_Wk, bk, p_K, MROWS, HDIM, HDIM, 1.0f, 0, 0, 0, 1);
    // V = K @ Wv^T + bv     (tf32 out)
    gemm_nt_pre<<<dim3(HDIM / 128, MROWS / 128, 1), 256>>>(
        p_K, p_Wv, bv, p_V, MROWS, HDIM, HDIM, 1.0f, 0, 0, 0, 1);

    // entire sequential LSTM in one persistent bf16 tensor-core launch
    lstm_bf16<<<128, 256, SM2_BYTES>>>(W_hh);

    // Q = Htf @ Wq^T + bq   (fast pre-converted path; tf32 out)
    gemm_nt_pre<<<dim3(HDIM / 128, MROWS / 128, 1), 256>>>(
        p_Htf, p_Wq, bq, p_Q, MROWS, HDIM, HDIM, 1.0f, 0, 0, 0, 1);

    // scores: per-batch S[t,s] = scale * Q[t,:]·K[s,:]  (fp32 out -> softmax)
    gemm_nt_pre<<<dim3(SENC / 128, SDEC / 128, B_), 256>>>(
        p_Q, p_K, nullptr, p_S, SDEC, SENC, HDIM, scale,
        (size_t)SDEC * HDIM, (size_t)SENC * HDIM, (size_t)SDEC * SENC, 0);

    softmax_warp<<<(B_ * SDEC) / 8, 256>>>(p_S);

    // context + h: HC = S@V + H  (tf32 out)
    gemm_nn_pre<<<dim3(HDIM / 128, SDEC / 128, B_), 256>>>(
        p_S, p_V, p_H, p_HC, SDEC, HDIM, SENC,
        (size_t)SDEC * SENC, (size_t)SENC * HDIM,
        (size_t)SDEC * HDIM, (size_t)SDEC * HDIM, 1);

    // out = HC @ Wfc^T + bfc  (fp32 final)
    gemm_nt_pre<<<dim3(ODIM / 128, MROWS / 128, 1), 256>>>(
        p_HC, p_Wfc, bfc, out, MROWS, ODIM, HDIM, 1.0f, 0, 0, 0, 0);
}